// round 12
// baseline (speedup 1.0000x reference)
#include <cuda_runtime.h>
#include <cuda_fp16.h>
#include <math.h>
#include <stdint.h>

#define TOK   2048
#define HD    1024
#define ID    1024
#define NE    32
#define TOPK  4
#define TWOI  2048
#define PAIRS (TOK*TOPK)
#define LIMITF 7.0f
#define ALPHAF 1.702f

// -------- device scratch --------
__device__ int   g_count[NE];
__device__ int   g_offset[NE];
__device__ int   g_cursor[NE];
__device__ int   g_topk_idx[TOK * TOPK];
__device__ float g_topk_w[TOK * TOPK];
__device__ int   g_pair_token[PAIRS];
__device__ int   g_pair_of[TOK * TOPK];
__device__ float g_act[(size_t)PAIRS * ID];
__device__ float g_y[(size_t)PAIRS * HD];

// -------- helpers --------
__device__ __forceinline__ void mma_f16(float* d, const uint32_t* a, const uint32_t* b) {
    asm volatile(
        "mma.sync.aligned.m16n8k16.row.col.f32.f16.f16.f32 "
        "{%0,%1,%2,%3}, {%4,%5,%6,%7}, {%8,%9}, {%0,%1,%2,%3};\n"
        : "+f"(d[0]), "+f"(d[1]), "+f"(d[2]), "+f"(d[3])
        : "r"(a[0]), "r"(a[1]), "r"(a[2]), "r"(a[3]),
          "r"(b[0]), "r"(b[1]));
}
__device__ __forceinline__ uint32_t h2u(__half2 h) { return *(uint32_t*)&h; }

// pack 16 consecutive-k floats (as 8 half2 words w[0..7], w[m]={f2m,f2m+1})
// into the permuted memory order [w0,w4,w1,w5,w2,w6,w3,w7]
__device__ __forceinline__ void perm_store(__half* dst, const uint32_t* w) {
    uint4 u0, u1;
    u0.x = w[0]; u0.y = w[4]; u0.z = w[1]; u0.w = w[5];
    u1.x = w[2]; u1.y = w[6]; u1.z = w[3]; u1.w = w[7];
    *(uint4*)dst       = u0;
    *(uint4*)(dst + 8) = u1;
}

// -------- grouped fp16 GEMM (both stages), 256 thr, 128x128 tile, BK=32 --------
// A smem [m][48] halves (2 chunks of 16k permuted + pad); B smem [n][48] same.
template<bool FIRST>
__global__ __launch_bounds__(256, 2) void moe_gemm(const float* __restrict__ x,
                                                   const float* __restrict__ W,
                                                   const float* __restrict__ gub) {
    const int LDBW = FIRST ? TWOI : HD;
    const int bx = blockIdx.x;
    const int e  = blockIdx.y >> 4;
    const int rt = blockIdx.y & 15;
    const int base = g_offset[e];
    const int cnt  = g_count[e];
    const int row0 = rt * 128;
    if (row0 >= cnt) return;

    __shared__ __align__(16) __half As[2][128][48];
    __shared__ __align__(16) __half Bs[2][128][48];

    const int tid  = threadIdx.x;
    const int lane = tid & 31;
    const int wid  = tid >> 5;
    const int wm   = wid >> 2;         // 0..1
    const int wn   = wid & 3;          // 0..3
    const int lr   = lane >> 2;        // 0..7
    const int lc   = lane & 3;         // 0..3

    // A staging: thread -> (m row tid>>1, k-chunk tid&1 of 16 floats)
    const int rowA   = tid >> 1;
    const int chunkA = tid & 1;
    int ar = row0 + rowA; if (ar >= cnt) ar = cnt - 1;
    const float* aRow;
    if (FIRST) aRow = x + (size_t)g_pair_token[base + ar] * HD + chunkA * 16;
    else       aRow = (const float*)g_act + (size_t)(base + ar) * ID + chunkA * 16;

    // B staging: thread -> (n col tid>>1, k-chunk tid&1 of 16 rows), strided loads
    const int nB     = tid >> 1;
    const int chunkB = tid & 1;
    const float* bCol = W + ((size_t)e * 1024 + chunkB * 16) * LDBW + bx * 128 + nB;

    float acc[4][4][4];
    #pragma unroll
    for (int i = 0; i < 4; i++)
        #pragma unroll
        for (int j = 0; j < 4; j++)
            #pragma unroll
            for (int q = 0; q < 4; q++) acc[i][j][q] = 0.f;

    // ---- prologue: k-tile 0 -> buf 0 ----
    {
        uint32_t wA[8], wB[8];
        #pragma unroll
        for (int m = 0; m < 4; m++) {
            float4 v = *(const float4*)(aRow + m * 4);
            wA[2 * m]     = h2u(__floats2half2_rn(v.x, v.y));
            wA[2 * m + 1] = h2u(__floats2half2_rn(v.z, v.w));
        }
        #pragma unroll
        for (int m = 0; m < 8; m++) {
            float b0 = bCol[(size_t)(2 * m) * LDBW];
            float b1 = bCol[(size_t)(2 * m + 1) * LDBW];
            wB[m] = h2u(__floats2half2_rn(b0, b1));
        }
        perm_store(&As[0][rowA][chunkA * 16], wA);
        perm_store(&Bs[0][nB][chunkB * 16], wB);
    }
    __syncthreads();

    const int NK = 32;   // 1024/32
    #pragma unroll 1
    for (int kt = 0; kt < NK; kt++) {
        // prefetch next k-tile into registers
        float4 pa[4];
        float pb[16];
        if (kt + 1 < NK) {
            const float* ap = aRow + (kt + 1) * 32;
            #pragma unroll
            for (int m = 0; m < 4; m++) pa[m] = *(const float4*)(ap + m * 4);
            const float* bp = bCol + (size_t)(kt + 1) * 32 * LDBW;
            #pragma unroll
            for (int j = 0; j < 16; j++) pb[j] = bp[(size_t)j * LDBW];
        }

        const int cur = kt & 1;
        #pragma unroll
        for (int kk = 0; kk < 2; kk++) {
            // B fragments: one LDS.64 per nt -> {b0, b1}
            uint32_t bf[4][2];
            #pragma unroll
            for (int nt = 0; nt < 4; nt++) {
                const int n = wn * 32 + nt * 8 + lr;
                uint2 v = *(const uint2*)&Bs[cur][n][kk * 16 + 4 * lc];
                bf[nt][0] = v.x; bf[nt][1] = v.y;
            }
            #pragma unroll
            for (int mt = 0; mt < 4; mt++) {
                const int r = wm * 64 + mt * 16 + lr;
                uint2 lo = *(const uint2*)&As[cur][r][kk * 16 + 4 * lc];      // a0, a2
                uint2 hi = *(const uint2*)&As[cur][r + 8][kk * 16 + 4 * lc];  // a1, a3
                uint32_t af[4] = { lo.x, hi.x, lo.y, hi.y };
                #pragma unroll
                for (int nt = 0; nt < 4; nt++)
                    mma_f16(acc[mt][nt], af, bf[nt]);
            }
        }

        if (kt + 1 < NK) {
            const int nb = (kt + 1) & 1;
            uint32_t wA[8], wB[8];
            #pragma unroll
            for (int m = 0; m < 4; m++) {
                wA[2 * m]     = h2u(__floats2half2_rn(pa[m].x, pa[m].y));
                wA[2 * m + 1] = h2u(__floats2half2_rn(pa[m].z, pa[m].w));
            }
            #pragma unroll
            for (int m = 0; m < 8; m++)
                wB[m] = h2u(__floats2half2_rn(pb[2 * m], pb[2 * m + 1]));
            perm_store(&As[nb][rowA][chunkA * 16], wA);
            perm_store(&Bs[nb][nB][chunkB * 16], wB);
        }
        __syncthreads();
    }

    // ---- epilogue (fragment layout identical to before) ----
    if (FIRST) {
        const float* gb = gub + (size_t)e * TWOI;
        #pragma unroll
        for (int mt = 0; mt < 4; mt++) {
            #pragma unroll
            for (int half = 0; half < 2; half++) {
                const int grow = row0 + wm * 64 + mt * 16 + lr + half * 8;
                if (grow < cnt) {
                    float* orow = g_act + (size_t)(base + grow) * ID;
                    #pragma unroll
                    for (int nt = 0; nt < 4; nt++) {
                        const int i = bx * 64 + wn * 16 + nt * 4 + lc;
                        float gate = acc[mt][nt][half * 2 + 0] + gb[2 * i];
                        float up   = acc[mt][nt][half * 2 + 1] + gb[2 * i + 1];
                        gate = fminf(gate, LIMITF);
                        up   = fminf(fmaxf(up, -LIMITF), LIMITF);
                        float glu = gate / (1.f + __expf(-gate * ALPHAF));
                        orow[i] = (up + 1.f) * glu;
                    }
                }
            }
        }
    } else {
        #pragma unroll
        for (int mt = 0; mt < 4; mt++) {
            #pragma unroll
            for (int half = 0; half < 2; half++) {
                const int grow = row0 + wm * 64 + mt * 16 + lr + half * 8;
                if (grow < cnt) {
                    float* orow = g_y + (size_t)(base + grow) * HD;
                    #pragma unroll
                    for (int nt = 0; nt < 4; nt++) {
                        const int c = bx * 128 + wn * 32 + nt * 8 + 2 * lc;
                        *(float2*)(orow + c) = make_float2(acc[mt][nt][half * 2 + 0],
                                                           acc[mt][nt][half * 2 + 1]);
                    }
                }
            }
        }
    }
}

// -------- K0: reset counters --------
__global__ void reset_kernel() {
    int i = threadIdx.x;
    if (i < NE) g_count[i] = 0;
}

// -------- K1: router --------
__global__ void router_kernel(const float* __restrict__ x,
                              const float* __restrict__ rw,
                              const float* __restrict__ rb,
                              float* __restrict__ scores_out) {
    const int t    = blockIdx.x;
    const int tid  = threadIdx.x;
    const int warp = tid >> 5;
    const int lane = tid & 31;

    __shared__ float logits[NE];
    const float* xr = x + (size_t)t * HD;

    for (int e = warp; e < NE; e += 8) {
        const float* w = rw + (size_t)e * HD;
        float s = 0.f;
        for (int h = lane; h < HD; h += 32) s += xr[h] * w[h];
        #pragma unroll
        for (int off = 16; off; off >>= 1) s += __shfl_down_sync(0xffffffffu, s, off);
        if (lane == 0) logits[e] = s + rb[e];
    }
    __syncthreads();

    if (warp == 0) {
        float cur = logits[lane];
        float sel_val[TOPK];
        int   sel_idx[TOPK];
        #pragma unroll
        for (int k = 0; k < TOPK; k++) {
            float bv = cur; int bi = lane;
            #pragma unroll
            for (int off = 16; off; off >>= 1) {
                float ov = __shfl_xor_sync(0xffffffffu, bv, off);
                int   oi = __shfl_xor_sync(0xffffffffu, bi, off);
                if (ov > bv || (ov == bv && oi < bi)) { bv = ov; bi = oi; }
            }
            sel_val[k] = bv; sel_idx[k] = bi;
            if (lane == bi) cur = -1e30f;
        }
        float m = sel_val[0];
        float ex[TOPK]; float sum = 0.f;
        #pragma unroll
        for (int k = 0; k < TOPK; k++) { ex[k] = expf(sel_val[k] - m); sum += ex[k]; }
        float inv = 1.f / sum;

        float sc = 0.f;
        #pragma unroll
        for (int k = 0; k < TOPK; k++) if (lane == sel_idx[k]) sc = ex[k] * inv;
        scores_out[(size_t)t * NE + lane] = sc;

        if (lane < TOPK) {
            g_topk_idx[t * TOPK + lane] = sel_idx[lane];
            g_topk_w[t * TOPK + lane]   = ex[lane] * inv;
            atomicAdd(&g_count[sel_idx[lane]], 1);
        }
    }
}

// -------- K2: prefix sum --------
__global__ void prefix_kernel() {
    if (threadIdx.x == 0) {
        int acc = 0;
        for (int e = 0; e < NE; e++) {
            g_offset[e] = acc;
            g_cursor[e] = acc;
            acc += g_count[e];
        }
    }
}

// -------- K3: scatter --------
__global__ void scatter_kernel() {
    int t = blockIdx.x * blockDim.x + threadIdx.x;
    if (t >= TOK) return;
    #pragma unroll
    for (int k = 0; k < TOPK; k++) {
        int e   = g_topk_idx[t * TOPK + k];
        int pos = atomicAdd(&g_cursor[e], 1);
        g_pair_token[pos] = t;
        g_pair_of[t * TOPK + k] = pos;
    }
}

// -------- K7: weighted combine + down bias --------
__global__ void combine_kernel(const float* __restrict__ db,
                               float* __restrict__ out) {
    size_t idx = (size_t)blockIdx.x * blockDim.x + threadIdx.x;
    if (idx >= (size_t)TOK * HD) return;
    int t = (int)(idx >> 10);
    int h = (int)(idx & 1023);
    float s = 0.f;
    #pragma unroll
    for (int k = 0; k < TOPK; k++) {
        int   p = g_pair_of[t * TOPK + k];
        int   e = g_topk_idx[t * TOPK + k];
        float w = g_topk_w[t * TOPK + k];
        s += w * (g_y[(size_t)p * HD + h] + db[(size_t)e * HD + h]);
    }
    out[(size_t)t * HD + h] = s;
}

// -------- launch --------
extern "C" void kernel_launch(void* const* d_in, const int* in_sizes, int n_in,
                              void* d_out, int out_size) {
    const float* hidden  = (const float*)d_in[0];
    const float* gate_up = (const float*)d_in[1];
    const float* gub     = (const float*)d_in[2];
    const float* down    = (const float*)d_in[3];
    const float* db      = (const float*)d_in[4];
    const float* rw      = (const float*)d_in[5];
    const float* rb      = (const float*)d_in[6];

    float* out_routed = (float*)d_out;
    float* out_scores = (float*)d_out + (size_t)TOK * HD;

    reset_kernel<<<1, 32>>>();
    router_kernel<<<TOK, 256>>>(hidden, rw, rb, out_scores);
    prefix_kernel<<<1, 32>>>();
    scatter_kernel<<<(TOK + 255) / 256, 256>>>();

    moe_gemm<true><<<dim3(16, NE * 16), 256>>>(hidden, gate_up, gub);
    moe_gemm<false><<<dim3(8, NE * 16), 256>>>(nullptr, down, nullptr);
    combine_kernel<<<((size_t)TOK * HD + 255) / 256, 256>>>(db, out_routed);
}

// round 13
// speedup vs baseline: 1.4673x; 1.4673x over previous
#include <cuda_runtime.h>
#include <cuda_fp16.h>
#include <math.h>
#include <stdint.h>

#define TOK   2048
#define HD    1024
#define ID    1024
#define NE    32
#define TOPK  4
#define TWOI  2048
#define PAIRS (TOK*TOPK)
#define LIMITF 7.0f
#define ALPHAF 1.702f

// -------- device scratch --------
__device__ int   g_count[NE];
__device__ int   g_offset[NE];
__device__ int   g_cursor[NE];
__device__ int   g_topk_idx[TOK * TOPK];
__device__ float g_topk_w[TOK * TOPK];
__device__ int   g_pair_token[PAIRS];
__device__ int   g_pair_of[TOK * TOPK];
__device__ float g_act[(size_t)PAIRS * ID];
__device__ float g_y[(size_t)PAIRS * HD];

// -------- helpers --------
__device__ __forceinline__ void mma_f16(float* d, const uint32_t* a, const uint32_t* b) {
    asm volatile(
        "mma.sync.aligned.m16n8k16.row.col.f32.f16.f16.f32 "
        "{%0,%1,%2,%3}, {%4,%5,%6,%7}, {%8,%9}, {%0,%1,%2,%3};\n"
        : "+f"(d[0]), "+f"(d[1]), "+f"(d[2]), "+f"(d[3])
        : "r"(a[0]), "r"(a[1]), "r"(a[2]), "r"(a[3]),
          "r"(b[0]), "r"(b[1]));
}
__device__ __forceinline__ uint32_t h2u(__half2 h) { return *(uint32_t*)&h; }
__device__ __forceinline__ uint4 f8_to_h8(float4 v0, float4 v1) {
    uint4 u;
    u.x = h2u(__floats2half2_rn(v0.x, v0.y));
    u.y = h2u(__floats2half2_rn(v0.z, v0.w));
    u.z = h2u(__floats2half2_rn(v1.x, v1.y));
    u.w = h2u(__floats2half2_rn(v1.z, v1.w));
    return u;
}
__device__ __forceinline__ void cp16(void* s, const void* g) {
    unsigned sa = (unsigned)__cvta_generic_to_shared(s);
    asm volatile("cp.async.cg.shared.global [%0], [%1], 16;\n" :: "r"(sa), "l"(g));
}
#define CP_COMMIT() asm volatile("cp.async.commit_group;\n" ::: "memory")
#define CP_WAIT2()  asm volatile("cp.async.wait_group 2;\n" ::: "memory")

// -------- grouped fp16 GEMM, 256 thr, 128x128 tile, BK=16 --------
// A: fp16 smem [2][128][24] via register staging (L2-hot source).
// B: fp32 smem [4][16][132] via 4-stage cp.async ring (DRAM-latency source);
//    fp32->fp16 pack happens at fragment load (free: loop is latency-bound).
template<bool FIRST>
__global__ __launch_bounds__(256, 2) void moe_gemm(const float* __restrict__ x,
                                                   const float* __restrict__ W,
                                                   const float* __restrict__ gub) {
    const int LDBW = FIRST ? TWOI : HD;
    const int bx = blockIdx.x;
    const int e  = blockIdx.y >> 4;
    const int rt = blockIdx.y & 15;
    const int base = g_offset[e];
    const int cnt  = g_count[e];
    const int row0 = rt * 128;
    if (row0 >= cnt) return;

    __shared__ __align__(16) __half As[2][128][24];
    __shared__ __align__(16) float  Bsf[4][16][132];

    const int tid  = threadIdx.x;
    const int lane = tid & 31;
    const int wid  = tid >> 5;
    const int wm   = wid >> 2;         // 0..1
    const int wn   = wid & 3;          // 0..3
    const int lr   = lane >> 2;        // 0..7
    const int lc   = lane & 3;         // 0..3

    // A staging: thread -> (m row tid>>1, k-half (tid&1)*8)
    const int rowA  = tid >> 1;
    const int halfA = (tid & 1) * 8;
    int ar = row0 + rowA; if (ar >= cnt) ar = cnt - 1;
    const float* aRow;
    if (FIRST) aRow = x + (size_t)g_pair_token[base + ar] * HD + halfA;
    else       aRow = (const float*)g_act + (size_t)(base + ar) * ID + halfA;

    // B staging via cp.async: thread -> (k row tid>>4, col chunk (tid&15)*8), 2x 16B
    const int rB = tid >> 4;           // 0..15
    const int cB = (tid & 15) * 8;     // 0..120
    const float* bSrc = W + ((size_t)e * 1024 + rB) * LDBW + bx * 128 + cB;

    float acc[4][4][4];
    #pragma unroll
    for (int i = 0; i < 4; i++)
        #pragma unroll
        for (int j = 0; j < 4; j++)
            #pragma unroll
            for (int q = 0; q < 4; q++) acc[i][j][q] = 0.f;

    const int NK = 64;   // 1024/16

    // ---- prologue: issue B stages 0..2; stage A tile 0 ----
    #pragma unroll
    for (int s = 0; s < 3; s++) {
        const float* src = bSrc + (size_t)s * 16 * LDBW;
        cp16(&Bsf[s][rB][cB],     src);
        cp16(&Bsf[s][rB][cB + 4], src + 4);
        CP_COMMIT();
    }
    {
        float4 a0 = *(const float4*)aRow;
        float4 a1 = *(const float4*)(aRow + 4);
        *(uint4*)&As[0][rowA][halfA] = f8_to_h8(a0, a1);
    }

    #pragma unroll 1
    for (int kt = 0; kt < NK; kt++) {
        // A register prefetch for kt+1
        float4 a0, a1;
        if (kt + 1 < NK) {
            const float* ap = aRow + (kt + 1) * 16;
            a0 = *(const float4*)ap;
            a1 = *(const float4*)(ap + 4);
        }

        CP_WAIT2();            // B stage kt complete (3 groups in flight)
        __syncthreads();       // all threads' copies + A stores visible

        const int ab = kt & 1;
        const int bs = kt & 3;

        // B fragments: fp32 loads + pack to half2 (conflict-free banks)
        uint32_t bf[4][2];
        #pragma unroll
        for (int nt = 0; nt < 4; nt++) {
            const int n = wn * 32 + nt * 8 + lr;
            float b00 = Bsf[bs][2 * lc][n];
            float b01 = Bsf[bs][2 * lc + 1][n];
            float b10 = Bsf[bs][2 * lc + 8][n];
            float b11 = Bsf[bs][2 * lc + 9][n];
            bf[nt][0] = h2u(__floats2half2_rn(b00, b01));
            bf[nt][1] = h2u(__floats2half2_rn(b10, b11));
        }
        #pragma unroll
        for (int mt = 0; mt < 4; mt++) {
            const int r = wm * 64 + mt * 16 + lr;
            uint32_t af[4];
            af[0] = *(const uint32_t*)&As[ab][r][2 * lc];
            af[1] = *(const uint32_t*)&As[ab][r + 8][2 * lc];
            af[2] = *(const uint32_t*)&As[ab][r][2 * lc + 8];
            af[3] = *(const uint32_t*)&As[ab][r + 8][2 * lc + 8];
            #pragma unroll
            for (int nt = 0; nt < 4; nt++)
                mma_f16(acc[mt][nt], af, bf[nt]);
        }

        // stage A(kt+1) into alternate buffer
        if (kt + 1 < NK)
            *(uint4*)&As[(kt + 1) & 1][rowA][halfA] = f8_to_h8(a0, a1);

        // issue B stage kt+3 (empty commit keeps group accounting uniform)
        if (kt + 3 < NK) {
            const float* src = bSrc + (size_t)(kt + 3) * 16 * LDBW;
            cp16(&Bsf[(kt + 3) & 3][rB][cB],     src);
            cp16(&Bsf[(kt + 3) & 3][rB][cB + 4], src + 4);
        }
        CP_COMMIT();
    }

    // ---- epilogue ----
    if (FIRST) {
        const float* gb = gub + (size_t)e * TWOI;
        #pragma unroll
        for (int mt = 0; mt < 4; mt++) {
            #pragma unroll
            for (int half = 0; half < 2; half++) {
                const int grow = row0 + wm * 64 + mt * 16 + lr + half * 8;
                if (grow < cnt) {
                    float* orow = g_act + (size_t)(base + grow) * ID;
                    #pragma unroll
                    for (int nt = 0; nt < 4; nt++) {
                        const int i = bx * 64 + wn * 16 + nt * 4 + lc;
                        float gate = acc[mt][nt][half * 2 + 0] + gb[2 * i];
                        float up   = acc[mt][nt][half * 2 + 1] + gb[2 * i + 1];
                        gate = fminf(gate, LIMITF);
                        up   = fminf(fmaxf(up, -LIMITF), LIMITF);
                        float glu = gate / (1.f + __expf(-gate * ALPHAF));
                        orow[i] = (up + 1.f) * glu;
                    }
                }
            }
        }
    } else {
        #pragma unroll
        for (int mt = 0; mt < 4; mt++) {
            #pragma unroll
            for (int half = 0; half < 2; half++) {
                const int grow = row0 + wm * 64 + mt * 16 + lr + half * 8;
                if (grow < cnt) {
                    float* orow = g_y + (size_t)(base + grow) * HD;
                    #pragma unroll
                    for (int nt = 0; nt < 4; nt++) {
                        const int c = bx * 128 + wn * 32 + nt * 8 + 2 * lc;
                        *(float2*)(orow + c) = make_float2(acc[mt][nt][half * 2 + 0],
                                                           acc[mt][nt][half * 2 + 1]);
                    }
                }
            }
        }
    }
}

// -------- K0: reset counters --------
__global__ void reset_kernel() {
    int i = threadIdx.x;
    if (i < NE) g_count[i] = 0;
}

// -------- K1: router --------
__global__ void router_kernel(const float* __restrict__ x,
                              const float* __restrict__ rw,
                              const float* __restrict__ rb,
                              float* __restrict__ scores_out) {
    const int t    = blockIdx.x;
    const int tid  = threadIdx.x;
    const int warp = tid >> 5;
    const int lane = tid & 31;

    __shared__ float logits[NE];
    const float* xr = x + (size_t)t * HD;

    for (int e = warp; e < NE; e += 8) {
        const float* w = rw + (size_t)e * HD;
        float s = 0.f;
        for (int h = lane; h < HD; h += 32) s += xr[h] * w[h];
        #pragma unroll
        for (int off = 16; off; off >>= 1) s += __shfl_down_sync(0xffffffffu, s, off);
        if (lane == 0) logits[e] = s + rb[e];
    }
    __syncthreads();

    if (warp == 0) {
        float cur = logits[lane];
        float sel_val[TOPK];
        int   sel_idx[TOPK];
        #pragma unroll
        for (int k = 0; k < TOPK; k++) {
            float bv = cur; int bi = lane;
            #pragma unroll
            for (int off = 16; off; off >>= 1) {
                float ov = __shfl_xor_sync(0xffffffffu, bv, off);
                int   oi = __shfl_xor_sync(0xffffffffu, bi, off);
                if (ov > bv || (ov == bv && oi < bi)) { bv = ov; bi = oi; }
            }
            sel_val[k] = bv; sel_idx[k] = bi;
            if (lane == bi) cur = -1e30f;
        }
        float m = sel_val[0];
        float ex[TOPK]; float sum = 0.f;
        #pragma unroll
        for (int k = 0; k < TOPK; k++) { ex[k] = expf(sel_val[k] - m); sum += ex[k]; }
        float inv = 1.f / sum;

        float sc = 0.f;
        #pragma unroll
        for (int k = 0; k < TOPK; k++) if (lane == sel_idx[k]) sc = ex[k] * inv;
        scores_out[(size_t)t * NE + lane] = sc;

        if (lane < TOPK) {
            g_topk_idx[t * TOPK + lane] = sel_idx[lane];
            g_topk_w[t * TOPK + lane]   = ex[lane] * inv;
            atomicAdd(&g_count[sel_idx[lane]], 1);
        }
    }
}

// -------- K2: prefix sum --------
__global__ void prefix_kernel() {
    if (threadIdx.x == 0) {
        int acc = 0;
        for (int e = 0; e < NE; e++) {
            g_offset[e] = acc;
            g_cursor[e] = acc;
            acc += g_count[e];
        }
    }
}

// -------- K3: scatter --------
__global__ void scatter_kernel() {
    int t = blockIdx.x * blockDim.x + threadIdx.x;
    if (t >= TOK) return;
    #pragma unroll
    for (int k = 0; k < TOPK; k++) {
        int e   = g_topk_idx[t * TOPK + k];
        int pos = atomicAdd(&g_cursor[e], 1);
        g_pair_token[pos] = t;
        g_pair_of[t * TOPK + k] = pos;
    }
}

// -------- K7: weighted combine + down bias --------
__global__ void combine_kernel(const float* __restrict__ db,
                               float* __restrict__ out) {
    size_t idx = (size_t)blockIdx.x * blockDim.x + threadIdx.x;
    if (idx >= (size_t)TOK * HD) return;
    int t = (int)(idx >> 10);
    int h = (int)(idx & 1023);
    float s = 0.f;
    #pragma unroll
    for (int k = 0; k < TOPK; k++) {
        int   p = g_pair_of[t * TOPK + k];
        int   e = g_topk_idx[t * TOPK + k];
        float w = g_topk_w[t * TOPK + k];
        s += w * (g_y[(size_t)p * HD + h] + db[(size_t)e * HD + h]);
    }
    out[(size_t)t * HD + h] = s;
}

// -------- launch --------
extern "C" void kernel_launch(void* const* d_in, const int* in_sizes, int n_in,
                              void* d_out, int out_size) {
    const float* hidden  = (const float*)d_in[0];
    const float* gate_up = (const float*)d_in[1];
    const float* gub     = (const float*)d_in[2];
    const float* down    = (const float*)d_in[3];
    const float* db      = (const float*)d_in[4];
    const float* rw      = (const float*)d_in[5];
    const float* rb      = (const float*)d_in[6];

    float* out_routed = (float*)d_out;
    float* out_scores = (float*)d_out + (size_t)TOK * HD;

    reset_kernel<<<1, 32>>>();
    router_kernel<<<TOK, 256>>>(hidden, rw, rb, out_scores);
    prefix_kernel<<<1, 32>>>();
    scatter_kernel<<<(TOK + 255) / 256, 256>>>();

    moe_gemm<true><<<dim3(16, NE * 16), 256>>>(hidden, gate_up, gub);
    moe_gemm<false><<<dim3(8, NE * 16), 256>>>(nullptr, down, nullptr);
    combine_kernel<<<((size_t)TOK * HD + 255) / 256, 256>>>(db, out_routed);
}